// round 2
// baseline (speedup 1.0000x reference)
#include <cuda_runtime.h>
#include <math.h>

#define WIN   11
#define RAD   5
#define TS    32
#define INW   42              // TS + 2*RAD
#define PIMG  44              // raw tile pitch (floats, mult of 4)
#define PC2   33              // hb pitch in float2 (odd -> bank-friendly stores)
#define NTHREADS 256
#define NBLOCKS  (16 * 16 * 48)

#define C1 0.0001f            // 0.01^2
#define C2 0.0009f            // 0.03^2

struct GW { float g[WIN]; };

// ---- packed f32x2 helpers (sm_100+) ----
typedef unsigned long long f2_t;
__device__ __forceinline__ f2_t pack2(float lo, float hi) {
    f2_t r; asm("mov.b64 %0, {%1, %2};" : "=l"(r) : "f"(lo), "f"(hi)); return r;
}
__device__ __forceinline__ void unpack2(f2_t v, float& lo, float& hi) {
    asm("mov.b64 {%0, %1}, %2;" : "=f"(lo), "=f"(hi) : "l"(v));
}
__device__ __forceinline__ void fma2(f2_t& d, f2_t a, f2_t b) {
    asm("fma.rn.f32x2 %0, %1, %2, %0;" : "+l"(d) : "l"(a), "l"(b));
}
__device__ __forceinline__ f2_t mul2(f2_t a, f2_t b) {
    f2_t r; asm("mul.rn.f32x2 %0, %1, %2;" : "=l"(r) : "l"(a), "l"(b)); return r;
}

// ---- scratch (no allocations allowed) ----
__device__ float        g_partials[NBLOCKS];
__device__ unsigned int g_done = 0;

// ---- shared memory layout (floats) ----
// raw: sA[42][44] sB[42][44] sF[42][44]
// hb : 4 packed-float2 arrays [42][PC2] : AB, AABB, AFBF, FFF
#define OFF_B    (INW * PIMG)                 // 1848
#define OFF_F    (2 * INW * PIMG)             // 3696
#define OFF_HB   (3 * INW * PIMG)             // 5544  (floats; 16B aligned)
#define HB_SZ    (INW * PC2 * 2)              // floats per packed array = 2772
#define OFF_RED  (OFF_HB + 4 * HB_SZ)         // 16632
#define SMEM_FLOATS (OFF_RED + 16)
#define SMEM_BYTES  (SMEM_FLOATS * 4)

__device__ __forceinline__ float ssim_val(float mu1, float mu2,
                                          float e11, float e22, float e12) {
    float mu1sq = mu1 * mu1;
    float mu2sq = mu2 * mu2;
    float mu12  = mu1 * mu2;
    float num = (2.0f * mu12 + C1) * (2.0f * (e12 - mu12) + C2);
    float den = (mu1sq + mu2sq + C1) * ((e11 - mu1sq) + (e22 - mu2sq) + C2);
    return __fdividef(num, den);
}

__global__ __launch_bounds__(NTHREADS, 2)
void ssim_tile_kernel(const float* __restrict__ A,
                      const float* __restrict__ B,
                      const float* __restrict__ F,
                      GW gw,
                      float* __restrict__ out) {
    extern __shared__ float sm[];
    float* sA = sm;
    float* sB = sm + OFF_B;
    float* sF = sm + OFF_F;
    f2_t* hbAB   = (f2_t*)(sm + OFF_HB);
    f2_t* hbAABB = (f2_t*)(sm + OFF_HB + HB_SZ);
    f2_t* hbAFBF = (f2_t*)(sm + OFF_HB + 2 * HB_SZ);
    f2_t* hbFFF  = (f2_t*)(sm + OFF_HB + 3 * HB_SZ);
    float* red   = sm + OFF_RED;

    const int tid = threadIdx.x;
    const int x0 = blockIdx.x * TS - RAD;
    const int y0 = blockIdx.y * TS - RAD;
    const size_t pbase = (size_t)blockIdx.z * (512 * 512);

    // packed Gaussian taps
    f2_t gg[WIN];
    #pragma unroll
    for (int k = 0; k < WIN; k++) gg[k] = pack2(gw.g[k], gw.g[k]);

    // ---- stage 42x42 raw tiles (zero-padded) ----
    #pragma unroll 2
    for (int i = tid; i < INW * INW; i += NTHREADS) {
        int r = i / INW, c = i - r * INW;
        int gx = x0 + c, gy = y0 + r;
        float a = 0.f, b = 0.f, f = 0.f;
        if ((unsigned)gx < 512u && (unsigned)gy < 512u) {
            size_t off = pbase + (size_t)gy * 512 + gx;
            a = A[off]; b = B[off]; f = F[off];
        }
        sA[r * PIMG + c] = a;
        sB[r * PIMG + c] = b;
        sF[r * PIMG + c] = f;
    }
    __syncthreads();

    // ---- horizontal pass: 42 rows x 8 col-groups of 4 outputs ----
    for (int i = tid; i < INW * 8; i += NTHREADS) {
        int r  = i >> 3;
        int cg = (i & 7) << 2;
        const float* ba = &sA[r * PIMG + cg];
        const float* bb = &sB[r * PIMG + cg];
        const float* bf = &sF[r * PIMG + cg];

        float a[16], b[16], f[16];
        #pragma unroll
        for (int q = 0; q < 4; q++) {
            float4 va = *(const float4*)(ba + 4 * q);
            float4 vb = *(const float4*)(bb + 4 * q);
            float4 vf = *(const float4*)(bf + 4 * q);
            a[4*q+0]=va.x; a[4*q+1]=va.y; a[4*q+2]=va.z; a[4*q+3]=va.w;
            b[4*q+0]=vb.x; b[4*q+1]=vb.y; b[4*q+2]=vb.z; b[4*q+3]=vb.w;
            f[4*q+0]=vf.x; f[4*q+1]=vf.y; f[4*q+2]=vf.z; f[4*q+3]=vf.w;
        }

        f2_t mAB[4], mAABB[4], mAFBF[4], mFFF[4];
        #pragma unroll
        for (int j = 0; j < 4; j++) { mAB[j]=0; mAABB[j]=0; mAFBF[j]=0; mFFF[j]=0; }

        #pragma unroll
        for (int ii = 0; ii < 14; ii++) {
            float av = a[ii], bv = b[ii], fv = f[ii];
            f2_t ab   = pack2(av, bv);
            f2_t aabb = mul2(ab, ab);
            f2_t ffp  = pack2(fv, fv);
            f2_t afbf = mul2(ab, ffp);
            f2_t fff  = pack2(fv, fv * fv);
            #pragma unroll
            for (int j = 0; j < 4; j++) {
                int k = ii - j;
                if (k >= 0 && k < WIN) {
                    fma2(mAB[j],   gg[k], ab);
                    fma2(mAABB[j], gg[k], aabb);
                    fma2(mAFBF[j], gg[k], afbf);
                    fma2(mFFF[j],  gg[k], fff);
                }
            }
        }
        int o = r * PC2 + cg;
        #pragma unroll
        for (int j = 0; j < 4; j++) {
            hbAB[o + j]   = mAB[j];
            hbAABB[o + j] = mAABB[j];
            hbAFBF[o + j] = mAFBF[j];
            hbFFF[o + j]  = mFFF[j];
        }
    }
    __syncthreads();

    // ---- vertical pass: each thread = 4 consecutive rows x 1 col ----
    const int vc = tid & 31;
    const int r0 = (tid >> 5) << 2;   // 0,4,...,28

    f2_t vAB[4], vAABB[4], vAFBF[4], vFFF[4];
    #pragma unroll
    for (int j = 0; j < 4; j++) { vAB[j]=0; vAABB[j]=0; vAFBF[j]=0; vFFF[j]=0; }

    #pragma unroll
    for (int ii = 0; ii < 14; ii++) {
        int o = (r0 + ii) * PC2 + vc;
        f2_t ab   = hbAB[o];
        f2_t aabb = hbAABB[o];
        f2_t afbf = hbAFBF[o];
        f2_t fff  = hbFFF[o];
        #pragma unroll
        for (int j = 0; j < 4; j++) {
            int k = ii - j;
            if (k >= 0 && k < WIN) {
                fma2(vAB[j],   gg[k], ab);
                fma2(vAABB[j], gg[k], aabb);
                fma2(vAFBF[j], gg[k], afbf);
                fma2(vFFF[j],  gg[k], fff);
            }
        }
    }

    // ---- SSIM for both pairs ----
    float local = 0.f;
    #pragma unroll
    for (int j = 0; j < 4; j++) {
        float muA, muB, eAA, eBB, eAF, eBF, muF, eFF;
        unpack2(vAB[j],   muA, muB);
        unpack2(vAABB[j], eAA, eBB);
        unpack2(vAFBF[j], eAF, eBF);
        unpack2(vFFF[j],  muF, eFF);
        local += ssim_val(muA, muF, eAA, eFF, eAF);
        local += ssim_val(muB, muF, eBB, eFF, eBF);
    }

    // ---- block reduction ----
    #pragma unroll
    for (int o = 16; o > 0; o >>= 1)
        local += __shfl_down_sync(0xffffffffu, local, o);
    if ((tid & 31) == 0) red[tid >> 5] = local;
    __syncthreads();

    const int bid = blockIdx.x + 16 * blockIdx.y + 256 * blockIdx.z;
    __shared__ bool is_last;
    if (tid == 0) {
        float v = 0.f;
        #pragma unroll
        for (int w = 0; w < 8; w++) v += red[w];
        g_partials[bid] = v;
        __threadfence();
        unsigned int old = atomicAdd(&g_done, 1u);
        is_last = (old == NBLOCKS - 1);
    }
    __syncthreads();

    // ---- last block: final reduction in double ----
    if (is_last) {
        double s = 0.0;
        for (int i = tid; i < NBLOCKS; i += NTHREADS)
            s += (double)__ldcg(&g_partials[i]);
        #pragma unroll
        for (int o = 16; o > 0; o >>= 1)
            s += __shfl_down_sync(0xffffffffu, s, o);
        double* redd = (double*)red;
        if ((tid & 31) == 0) redd[tid >> 5] = s;
        __syncthreads();
        if (tid == 0) {
            double t = 0.0;
            #pragma unroll
            for (int w = 0; w < 8; w++) t += redd[w];
            out[0] = (float)(0.5 * t / 12582912.0);
            g_done = 0;   // reset for next invocation
        }
    }
}

extern "C" void kernel_launch(void* const* d_in, const int* in_sizes, int n_in,
                              void* d_out, int out_size) {
    const float* A = (const float*)d_in[0];
    const float* B = (const float*)d_in[1];
    const float* F = (const float*)d_in[2];

    GW gw;
    double gd[WIN], s = 0.0;
    for (int i = 0; i < WIN; i++) {
        double d = (double)(i - RAD);
        gd[i] = exp(-(d * d) / (2.0 * 1.5 * 1.5));
        s += gd[i];
    }
    for (int i = 0; i < WIN; i++) gw.g[i] = (float)(gd[i] / s);

    cudaFuncSetAttribute(ssim_tile_kernel,
                         cudaFuncAttributeMaxDynamicSharedMemorySize, SMEM_BYTES);

    dim3 grid(512 / TS, 512 / TS, 16 * 3);
    ssim_tile_kernel<<<grid, NTHREADS, SMEM_BYTES>>>(A, B, F, gw, (float*)d_out);
}

// round 3
// speedup vs baseline: 1.2810x; 1.2810x over previous
#include <cuda_runtime.h>
#include <math.h>

#define WIN   11
#define RAD   5
#define TS    32
#define INW   42              // TS + 2*RAD
#define PAB   43              // packed (A,B) pitch in f2 units (odd)
#define PF    44              // scalar F pitch in floats
#define PC2   33              // hb pitch in f2 units (odd)
#define NTHREADS 256
#define NBLOCKS  (16 * 16 * 48)

#define C1 0.0001f            // 0.01^2
#define C2 0.0009f            // 0.03^2

struct GW { float g[WIN]; };

// ---- packed f32x2 helpers (sm_100+) ----
typedef unsigned long long f2_t;
__device__ __forceinline__ f2_t pack2(float lo, float hi) {
    f2_t r; asm("mov.b64 %0, {%1, %2};" : "=l"(r) : "f"(lo), "f"(hi)); return r;
}
__device__ __forceinline__ void unpack2(f2_t v, float& lo, float& hi) {
    asm("mov.b64 {%0, %1}, %2;" : "=f"(lo), "=f"(hi) : "l"(v));
}
__device__ __forceinline__ void fma2(f2_t& d, f2_t a, f2_t b) {
    asm("fma.rn.f32x2 %0, %1, %2, %0;" : "+l"(d) : "l"(a), "l"(b));
}
__device__ __forceinline__ f2_t mul2(f2_t a, f2_t b) {
    f2_t r; asm("mul.rn.f32x2 %0, %1, %2;" : "=l"(r) : "l"(a), "l"(b)); return r;
}

// ---- scratch (no allocations allowed) ----
__device__ float        g_partials[NBLOCKS];
__device__ unsigned int g_done = 0;

// ---- shared memory layout (floats) ----
// sAB : [42][43] f2    (packed A,B per pixel)
// sF  : [42][44] float
// hb  : 4 f2 arrays [42][33] : AB, AABB, AFBF, FFF(=F,F^2)
#define OFF_F    (INW * PAB * 2)                 // 3612
#define OFF_HB   (OFF_F + INW * PF)              // 5460
#define HB_SZ    (INW * PC2 * 2)                 // 2772 floats per array
#define OFF_RED  (OFF_HB + 4 * HB_SZ)            // 16548
#define SMEM_FLOATS (OFF_RED + 16)
#define SMEM_BYTES  (SMEM_FLOATS * 4)

__device__ __forceinline__ float ssim_val(float mu1, float mu2,
                                          float e11, float e22, float e12) {
    float mu1sq = mu1 * mu1;
    float mu2sq = mu2 * mu2;
    float mu12  = mu1 * mu2;
    float num = (2.0f * mu12 + C1) * (2.0f * (e12 - mu12) + C2);
    float den = (mu1sq + mu2sq + C1) * ((e11 - mu1sq) + (e22 - mu2sq) + C2);
    return __fdividef(num, den);
}

__global__ __launch_bounds__(NTHREADS, 3)
void ssim_tile_kernel(const float* __restrict__ A,
                      const float* __restrict__ B,
                      const float* __restrict__ F,
                      GW gw,
                      float* __restrict__ out) {
    extern __shared__ float sm[];
    f2_t*  sAB = (f2_t*)sm;
    float* sF  = sm + OFF_F;
    f2_t* hbAB   = (f2_t*)(sm + OFF_HB);
    f2_t* hbAABB = (f2_t*)(sm + OFF_HB + HB_SZ);
    f2_t* hbAFBF = (f2_t*)(sm + OFF_HB + 2 * HB_SZ);
    f2_t* hbFFF  = (f2_t*)(sm + OFF_HB + 3 * HB_SZ);
    float* red   = sm + OFF_RED;

    const int tid = threadIdx.x;
    const int x0 = blockIdx.x * TS - RAD;
    const int y0 = blockIdx.y * TS - RAD;
    const size_t pbase = (size_t)blockIdx.z * (512 * 512);

    // packed Gaussian taps
    f2_t gg[WIN];
    #pragma unroll
    for (int k = 0; k < WIN; k++) gg[k] = pack2(gw.g[k], gw.g[k]);

    // ---- stage raw tiles: (A,B) packed + F scalar, zero-padded ----
    for (int i = tid; i < INW * INW; i += NTHREADS) {
        int r = i / INW, c = i - r * INW;
        int gx = x0 + c, gy = y0 + r;
        float a = 0.f, b = 0.f, f = 0.f;
        if ((unsigned)gx < 512u && (unsigned)gy < 512u) {
            size_t off = pbase + (size_t)gy * 512 + gx;
            a = A[off]; b = B[off]; f = F[off];
        }
        sAB[r * PAB + c] = pack2(a, b);
        sF[r * PF + c] = f;
    }
    __syncthreads();

    // ---- horizontal pass: 42 rows x 16 groups of 2 outputs = 672 items ----
    for (int i = tid; i < INW * 16; i += NTHREADS) {
        int r  = i >> 4;
        int c0 = (i & 15) << 1;
        const f2_t*  pab = sAB + r * PAB + c0;
        const float* pf  = sF + r * PF + c0;

        f2_t aAB[2]   = {0, 0};
        f2_t aAABB[2] = {0, 0};
        f2_t aAFBF[2] = {0, 0};
        f2_t aFFF[2]  = {0, 0};

        #pragma unroll
        for (int ii = 0; ii < 12; ii++) {
            f2_t  ab = pab[ii];
            float fv = pf[ii];
            f2_t ffp  = pack2(fv, fv);
            f2_t fff  = pack2(fv, fv * fv);
            f2_t aabb = mul2(ab, ab);
            f2_t afbf = mul2(ab, ffp);
            #pragma unroll
            for (int j = 0; j < 2; j++) {
                int k = ii - j;
                if (k >= 0 && k < WIN) {
                    fma2(aAB[j],   gg[k], ab);
                    fma2(aAABB[j], gg[k], aabb);
                    fma2(aAFBF[j], gg[k], afbf);
                    fma2(aFFF[j],  gg[k], fff);
                }
            }
        }
        int o = r * PC2 + c0;
        #pragma unroll
        for (int j = 0; j < 2; j++) {
            hbAB[o + j]   = aAB[j];
            hbAABB[o + j] = aAABB[j];
            hbAFBF[o + j] = aAFBF[j];
            hbFFF[o + j]  = aFFF[j];
        }
    }
    __syncthreads();

    // ---- vertical pass: each thread = 4 consecutive rows x 1 col ----
    const int vc = tid & 31;
    const int r0 = (tid >> 5) << 2;   // 0,4,...,28

    f2_t vAB[4], vAABB[4], vAFBF[4], vFFF[4];
    #pragma unroll
    for (int j = 0; j < 4; j++) { vAB[j]=0; vAABB[j]=0; vAFBF[j]=0; vFFF[j]=0; }

    #pragma unroll
    for (int ii = 0; ii < 14; ii++) {
        int o = (r0 + ii) * PC2 + vc;
        f2_t ab   = hbAB[o];
        f2_t aabb = hbAABB[o];
        f2_t afbf = hbAFBF[o];
        f2_t fff  = hbFFF[o];
        #pragma unroll
        for (int j = 0; j < 4; j++) {
            int k = ii - j;
            if (k >= 0 && k < WIN) {
                fma2(vAB[j],   gg[k], ab);
                fma2(vAABB[j], gg[k], aabb);
                fma2(vAFBF[j], gg[k], afbf);
                fma2(vFFF[j],  gg[k], fff);
            }
        }
    }

    // ---- SSIM for both pairs ----
    float local = 0.f;
    #pragma unroll
    for (int j = 0; j < 4; j++) {
        float muA, muB, eAA, eBB, eAF, eBF, muF, eFF;
        unpack2(vAB[j],   muA, muB);
        unpack2(vAABB[j], eAA, eBB);
        unpack2(vAFBF[j], eAF, eBF);
        unpack2(vFFF[j],  muF, eFF);
        local += ssim_val(muA, muF, eAA, eFF, eAF);
        local += ssim_val(muB, muF, eBB, eFF, eBF);
    }

    // ---- block reduction ----
    #pragma unroll
    for (int o = 16; o > 0; o >>= 1)
        local += __shfl_down_sync(0xffffffffu, local, o);
    if ((tid & 31) == 0) red[tid >> 5] = local;
    __syncthreads();

    const int bid = blockIdx.x + 16 * blockIdx.y + 256 * blockIdx.z;
    __shared__ bool is_last;
    if (tid == 0) {
        float v = 0.f;
        #pragma unroll
        for (int w = 0; w < 8; w++) v += red[w];
        g_partials[bid] = v;
        __threadfence();
        unsigned int old = atomicAdd(&g_done, 1u);
        is_last = (old == NBLOCKS - 1);
    }
    __syncthreads();

    // ---- last block: final reduction in double ----
    if (is_last) {
        double s = 0.0;
        for (int i = tid; i < NBLOCKS; i += NTHREADS)
            s += (double)__ldcg(&g_partials[i]);
        #pragma unroll
        for (int o = 16; o > 0; o >>= 1)
            s += __shfl_down_sync(0xffffffffu, s, o);
        double* redd = (double*)red;
        if ((tid & 31) == 0) redd[tid >> 5] = s;
        __syncthreads();
        if (tid == 0) {
            double t = 0.0;
            #pragma unroll
            for (int w = 0; w < 8; w++) t += redd[w];
            out[0] = (float)(0.5 * t / 12582912.0);
            g_done = 0;   // reset for next invocation
        }
    }
}

extern "C" void kernel_launch(void* const* d_in, const int* in_sizes, int n_in,
                              void* d_out, int out_size) {
    const float* A = (const float*)d_in[0];
    const float* B = (const float*)d_in[1];
    const float* F = (const float*)d_in[2];

    GW gw;
    double gd[WIN], s = 0.0;
    for (int i = 0; i < WIN; i++) {
        double d = (double)(i - RAD);
        gd[i] = exp(-(d * d) / (2.0 * 1.5 * 1.5));
        s += gd[i];
    }
    for (int i = 0; i < WIN; i++) gw.g[i] = (float)(gd[i] / s);

    cudaFuncSetAttribute(ssim_tile_kernel,
                         cudaFuncAttributeMaxDynamicSharedMemorySize, SMEM_BYTES);

    dim3 grid(512 / TS, 512 / TS, 16 * 3);
    ssim_tile_kernel<<<grid, NTHREADS, SMEM_BYTES>>>(A, B, F, gw, (float*)d_out);
}

// round 4
// speedup vs baseline: 1.3065x; 1.0199x over previous
#include <cuda_runtime.h>
#include <math.h>

#define WIN   11
#define RAD   5
#define TSX   32
#define TSY   24
#define INWX  42              // TSX + 2*RAD
#define INWY  34              // TSY + 2*RAD
#define PAB   43              // packed (A,B) pitch in f2 units (odd)
#define PF    44              // scalar F pitch in floats
#define PHB   33              // hb pitch in ulonglong2 units (odd)
#define NTHREADS 256
#define GRIDY 22              // ceil(512/24)
#define NBLOCKS  (16 * GRIDY * 48)

#define C1 0.0001f
#define C2 0.0009f

struct GW { float g[WIN]; };

typedef unsigned long long f2_t;
__device__ __forceinline__ f2_t pack2(float lo, float hi) {
    f2_t r; asm("mov.b64 %0, {%1, %2};" : "=l"(r) : "f"(lo), "f"(hi)); return r;
}
__device__ __forceinline__ void unpack2(f2_t v, float& lo, float& hi) {
    asm("mov.b64 {%0, %1}, %2;" : "=f"(lo), "=f"(hi) : "l"(v));
}
__device__ __forceinline__ void fma2(f2_t& d, f2_t a, f2_t b) {
    asm("fma.rn.f32x2 %0, %1, %2, %0;" : "+l"(d) : "l"(a), "l"(b));
}
__device__ __forceinline__ f2_t mul2(f2_t a, f2_t b) {
    f2_t r; asm("mul.rn.f32x2 %0, %1, %2;" : "=l"(r) : "l"(a), "l"(b)); return r;
}

__device__ float        g_partials[NBLOCKS];
__device__ unsigned int g_done = 0;

// ---- shared layout (float units) ----
// sAB : f2  [34][43]  = 2924 floats
// sF  : f32 [34][44]  = 1496 floats
// hb0 : ull2[34][33]  (AB, AABB)   = 4488 floats
// hb1 : ull2[34][33]  (AFBF, FFF)  = 4488 floats
#define OFF_F    2924
#define OFF_HB0  4420
#define OFF_HB1  8908
#define OFF_RED  13396
#define SMEM_FLOATS (OFF_RED + 16)
#define SMEM_BYTES  (SMEM_FLOATS * 4)   // 53648

__device__ __forceinline__ float ssim_val(float mu1, float mu2,
                                          float e11, float e22, float e12) {
    float mu1sq = mu1 * mu1;
    float mu2sq = mu2 * mu2;
    float mu12  = mu1 * mu2;
    float num = (2.0f * mu12 + C1) * (2.0f * (e12 - mu12) + C2);
    float den = (mu1sq + mu2sq + C1) * ((e11 - mu1sq) + (e22 - mu2sq) + C2);
    return __fdividef(num, den);
}

// symmetric tap fetch: g[k] == g[10-k], 6 packed regs
#define GSYM(k) gg[(k) < 6 ? (k) : 10 - (k)]

__global__ __launch_bounds__(NTHREADS, 4)
void ssim_tile_kernel(const float* __restrict__ A,
                      const float* __restrict__ B,
                      const float* __restrict__ F,
                      GW gw,
                      float* __restrict__ out) {
    extern __shared__ float sm[];
    f2_t*       sAB = (f2_t*)sm;
    float*      sF  = sm + OFF_F;
    ulonglong2* hb0 = (ulonglong2*)(sm + OFF_HB0);
    ulonglong2* hb1 = (ulonglong2*)(sm + OFF_HB1);
    float*      red = sm + OFF_RED;

    const int tid = threadIdx.x;
    const int x0 = blockIdx.x * TSX - RAD;
    const int y0 = blockIdx.y * TSY - RAD;
    const size_t pbase = (size_t)blockIdx.z * (512 * 512);

    f2_t gg[6];
    #pragma unroll
    for (int k = 0; k < 6; k++) gg[k] = pack2(gw.g[k], gw.g[k]);

    // ---- stage raw: (A,B) packed + F scalar, zero-padded ----
    for (int i = tid; i < INWY * INWX; i += NTHREADS) {
        int r = i / INWX, c = i - r * INWX;
        int gx = x0 + c, gy = y0 + r;
        float a = 0.f, b = 0.f, f = 0.f;
        if ((unsigned)gx < 512u && (unsigned)gy < 512u) {
            size_t off = pbase + (size_t)gy * 512 + gx;
            a = A[off]; b = B[off]; f = F[off];
        }
        sAB[r * PAB + c] = pack2(a, b);
        sF[r * PF + c] = f;
    }
    __syncthreads();

    // ---- horizontal pass: 34 rows x 16 groups of 2 outputs = 544 items ----
    for (int i = tid; i < INWY * 16; i += NTHREADS) {
        int r  = i >> 4;
        int c0 = (i & 15) << 1;
        const f2_t*  pab = sAB + r * PAB + c0;
        const float* pf  = sF + r * PF + c0;

        f2_t aAB[2]   = {0, 0};
        f2_t aAABB[2] = {0, 0};
        f2_t aAFBF[2] = {0, 0};
        f2_t aFFF[2]  = {0, 0};

        #pragma unroll
        for (int ii = 0; ii < 12; ii++) {
            f2_t  ab = pab[ii];
            float fv = pf[ii];
            f2_t ffp  = pack2(fv, fv);
            f2_t fff  = pack2(fv, fv * fv);
            f2_t aabb = mul2(ab, ab);
            f2_t afbf = mul2(ab, ffp);
            #pragma unroll
            for (int j = 0; j < 2; j++) {
                int k = ii - j;
                if (k >= 0 && k < WIN) {
                    fma2(aAB[j],   GSYM(k), ab);
                    fma2(aAABB[j], GSYM(k), aabb);
                    fma2(aAFBF[j], GSYM(k), afbf);
                    fma2(aFFF[j],  GSYM(k), fff);
                }
            }
        }
        int o = r * PHB + c0;
        #pragma unroll
        for (int j = 0; j < 2; j++) {
            hb0[o + j] = make_ulonglong2(aAB[j], aAABB[j]);
            hb1[o + j] = make_ulonglong2(aAFBF[j], aFFF[j]);
        }
    }
    __syncthreads();

    // ---- vertical pass: warps 0..5, thread = 1 col x 4 rows ----
    float local = 0.f;
    if (tid < 192) {
        const int vc = tid & 31;
        const int r0 = (tid >> 5) << 2;   // 0,4,...,20

        f2_t vAB[4], vAABB[4], vAFBF[4], vFFF[4];
        #pragma unroll
        for (int j = 0; j < 4; j++) { vAB[j]=0; vAABB[j]=0; vAFBF[j]=0; vFFF[j]=0; }

        #pragma unroll
        for (int ii = 0; ii < 14; ii++) {
            int o = (r0 + ii) * PHB + vc;
            ulonglong2 h0 = hb0[o];
            ulonglong2 h1 = hb1[o];
            #pragma unroll
            for (int j = 0; j < 4; j++) {
                int k = ii - j;
                if (k >= 0 && k < WIN) {
                    fma2(vAB[j],   GSYM(k), h0.x);
                    fma2(vAABB[j], GSYM(k), h0.y);
                    fma2(vAFBF[j], GSYM(k), h1.x);
                    fma2(vFFF[j],  GSYM(k), h1.y);
                }
            }
        }

        const int gy_base = blockIdx.y * TSY + r0;
        #pragma unroll
        for (int j = 0; j < 4; j++) {
            if (gy_base + j < 512) {
                float muA, muB, eAA, eBB, eAF, eBF, muF, eFF;
                unpack2(vAB[j],   muA, muB);
                unpack2(vAABB[j], eAA, eBB);
                unpack2(vAFBF[j], eAF, eBF);
                unpack2(vFFF[j],  muF, eFF);
                local += ssim_val(muA, muF, eAA, eFF, eAF);
                local += ssim_val(muB, muF, eBB, eFF, eBF);
            }
        }
    }

    // ---- block reduction ----
    #pragma unroll
    for (int o = 16; o > 0; o >>= 1)
        local += __shfl_down_sync(0xffffffffu, local, o);
    if ((tid & 31) == 0) red[tid >> 5] = local;
    __syncthreads();

    const int bid = blockIdx.x + 16 * blockIdx.y + (16 * GRIDY) * blockIdx.z;
    __shared__ bool is_last;
    if (tid == 0) {
        float v = 0.f;
        #pragma unroll
        for (int w = 0; w < 8; w++) v += red[w];
        g_partials[bid] = v;
        __threadfence();
        unsigned int old = atomicAdd(&g_done, 1u);
        is_last = (old == NBLOCKS - 1);
    }
    __syncthreads();

    if (is_last) {
        double s = 0.0;
        for (int i = tid; i < NBLOCKS; i += NTHREADS)
            s += (double)__ldcg(&g_partials[i]);
        #pragma unroll
        for (int o = 16; o > 0; o >>= 1)
            s += __shfl_down_sync(0xffffffffu, s, o);
        double* redd = (double*)red;
        if ((tid & 31) == 0) redd[tid >> 5] = s;
        __syncthreads();
        if (tid == 0) {
            double t = 0.0;
            #pragma unroll
            for (int w = 0; w < 8; w++) t += redd[w];
            out[0] = (float)(0.5 * t / 12582912.0);
            g_done = 0;
        }
    }
}

extern "C" void kernel_launch(void* const* d_in, const int* in_sizes, int n_in,
                              void* d_out, int out_size) {
    const float* A = (const float*)d_in[0];
    const float* B = (const float*)d_in[1];
    const float* F = (const float*)d_in[2];

    GW gw;
    double gd[WIN], s = 0.0;
    for (int i = 0; i < WIN; i++) {
        double d = (double)(i - RAD);
        gd[i] = exp(-(d * d) / (2.0 * 1.5 * 1.5));
        s += gd[i];
    }
    for (int i = 0; i < WIN; i++) gw.g[i] = (float)(gd[i] / s);

    cudaFuncSetAttribute(ssim_tile_kernel,
                         cudaFuncAttributeMaxDynamicSharedMemorySize, SMEM_BYTES);

    dim3 grid(512 / TSX, GRIDY, 16 * 3);
    ssim_tile_kernel<<<grid, NTHREADS, SMEM_BYTES>>>(A, B, F, gw, (float*)d_out);
}

// round 5
// speedup vs baseline: 1.4149x; 1.0830x over previous
#include <cuda_runtime.h>
#include <math.h>

#define WIN   11
#define RAD   5
#define TSX   32
#define TSY   24
#define INWX  42              // TSX + 2*RAD
#define INWY  34              // TSY + 2*RAD
#define PAB   43              // packed (A,B) pitch in f2 units (ODD -> conflict-free row-stride)
#define PF    45              // scalar F pitch in floats (ODD)
#define PHB   33              // hb pitch in ulonglong2 units (ODD)
#define NTHREADS 256
#define GRIDY 22              // ceil(512/24)
#define NBLOCKS  (16 * GRIDY * 48)

#define C1 0.0001f
#define C2 0.0009f

struct GW { float g[WIN]; };

typedef unsigned long long f2_t;
__device__ __forceinline__ f2_t pack2(float lo, float hi) {
    f2_t r; asm("mov.b64 %0, {%1, %2};" : "=l"(r) : "f"(lo), "f"(hi)); return r;
}
__device__ __forceinline__ void unpack2(f2_t v, float& lo, float& hi) {
    asm("mov.b64 {%0, %1}, %2;" : "=f"(lo), "=f"(hi) : "l"(v));
}
__device__ __forceinline__ void fma2(f2_t& d, f2_t a, f2_t b) {
    asm("fma.rn.f32x2 %0, %1, %2, %0;" : "+l"(d) : "l"(a), "l"(b));
}
__device__ __forceinline__ f2_t mul2(f2_t a, f2_t b) {
    f2_t r; asm("mul.rn.f32x2 %0, %1, %2;" : "=l"(r) : "l"(a), "l"(b)); return r;
}

__device__ float        g_partials[NBLOCKS];
__device__ unsigned int g_done = 0;

// ---- shared layout (float units) ----
// sAB : f2  [34][43] = 2924 floats
// sF  : f32 [34][45] = 1530 floats
// hb0 : ull2[34][33] (AB, AABB)  = 4488 floats
// hb1 : ull2[34][33] (AFBF, FFF) = 4488 floats
#define OFF_F    2924
#define OFF_HB0  4456          // 16B aligned
#define OFF_HB1  (OFF_HB0 + 4488)
#define OFF_RED  (OFF_HB1 + 4488)
#define SMEM_FLOATS (OFF_RED + 16)
#define SMEM_BYTES  (SMEM_FLOATS * 4)   // 53792 -> 4 CTAs/SM

__device__ __forceinline__ float ssim_val(float mu1, float mu2,
                                          float e11, float e22, float e12) {
    float mu1sq = mu1 * mu1;
    float mu2sq = mu2 * mu2;
    float mu12  = mu1 * mu2;
    float num = (2.0f * mu12 + C1) * (2.0f * (e12 - mu12) + C2);
    float den = (mu1sq + mu2sq + C1) * ((e11 - mu1sq) + (e22 - mu2sq) + C2);
    return __fdividef(num, den);
}

// symmetric taps: g[k] == g[10-k]
#define GSYM(k) gg[(k) < 6 ? (k) : 10 - (k)]

__global__ __launch_bounds__(NTHREADS, 4)
void ssim_tile_kernel(const float* __restrict__ A,
                      const float* __restrict__ B,
                      const float* __restrict__ F,
                      GW gw,
                      float* __restrict__ out) {
    extern __shared__ float sm[];
    f2_t*       sAB = (f2_t*)sm;
    float*      sF  = sm + OFF_F;
    ulonglong2* hb0 = (ulonglong2*)(sm + OFF_HB0);
    ulonglong2* hb1 = (ulonglong2*)(sm + OFF_HB1);
    float*      red = sm + OFF_RED;

    const int tid = threadIdx.x;
    const int x0 = blockIdx.x * TSX - RAD;
    const int y0 = blockIdx.y * TSY - RAD;
    const size_t pbase = (size_t)blockIdx.z * (512 * 512);

    f2_t gg[6];
    #pragma unroll
    for (int k = 0; k < 6; k++) gg[k] = pack2(gw.g[k], gw.g[k]);

    // ---- stage raw: (A,B) packed + F scalar, zero-padded ----
    for (int i = tid; i < INWY * INWX; i += NTHREADS) {
        int r = i / INWX, c = i - r * INWX;
        int gx = x0 + c, gy = y0 + r;
        float a = 0.f, b = 0.f, f = 0.f;
        if ((unsigned)gx < 512u && (unsigned)gy < 512u) {
            size_t off = pbase + (size_t)gy * 512 + gx;
            a = A[off]; b = B[off]; f = F[off];
        }
        sAB[r * PAB + c] = pack2(a, b);
        sF[r * PF + c] = f;
    }
    __syncthreads();

    // ---- horizontal pass: 544 items, lanes walk ROWS (conflict-free LDS) ----
    for (int i = tid; i < INWY * 16; i += NTHREADS) {
        int g  = i / INWY;           // column group 0..15
        int r  = i - g * INWY;       // row 0..33  (consecutive lanes -> consecutive rows)
        int c0 = g << 1;
        const f2_t*  pab = sAB + r * PAB + c0;
        const float* pf  = sF + r * PF + c0;

        f2_t aAB[2]   = {0, 0};
        f2_t aAABB[2] = {0, 0};
        f2_t aAFBF[2] = {0, 0};
        f2_t aFFF[2]  = {0, 0};

        #pragma unroll
        for (int ii = 0; ii < 12; ii++) {
            f2_t  ab = pab[ii];
            float fv = pf[ii];
            f2_t ffp  = pack2(fv, fv);
            f2_t fff  = pack2(fv, fv * fv);
            f2_t aabb = mul2(ab, ab);
            f2_t afbf = mul2(ab, ffp);
            #pragma unroll
            for (int j = 0; j < 2; j++) {
                int k = ii - j;
                if (k >= 0 && k < WIN) {
                    fma2(aAB[j],   GSYM(k), ab);
                    fma2(aAABB[j], GSYM(k), aabb);
                    fma2(aAFBF[j], GSYM(k), afbf);
                    fma2(aFFF[j],  GSYM(k), fff);
                }
            }
        }
        int o = r * PHB + c0;
        #pragma unroll
        for (int j = 0; j < 2; j++) {
            hb0[o + j] = make_ulonglong2(aAB[j], aAABB[j]);
            hb1[o + j] = make_ulonglong2(aAFBF[j], aFFF[j]);
        }
    }
    __syncthreads();

    // ---- vertical pass: 256 threads, thread = 1 col x 3 rows (balanced) ----
    const int vc = tid & 31;
    const int r0 = (tid >> 5) * 3;    // 0,3,...,21

    f2_t vAB[3], vAABB[3], vAFBF[3], vFFF[3];
    #pragma unroll
    for (int j = 0; j < 3; j++) { vAB[j]=0; vAABB[j]=0; vAFBF[j]=0; vFFF[j]=0; }

    #pragma unroll
    for (int ii = 0; ii < 13; ii++) {
        int o = (r0 + ii) * PHB + vc;
        ulonglong2 h0 = hb0[o];
        ulonglong2 h1 = hb1[o];
        #pragma unroll
        for (int j = 0; j < 3; j++) {
            int k = ii - j;
            if (k >= 0 && k < WIN) {
                fma2(vAB[j],   GSYM(k), h0.x);
                fma2(vAABB[j], GSYM(k), h0.y);
                fma2(vAFBF[j], GSYM(k), h1.x);
                fma2(vFFF[j],  GSYM(k), h1.y);
            }
        }
    }

    float local = 0.f;
    const int gy_base = blockIdx.y * TSY + r0;
    #pragma unroll
    for (int j = 0; j < 3; j++) {
        if (gy_base + j < 512) {
            float muA, muB, eAA, eBB, eAF, eBF, muF, eFF;
            unpack2(vAB[j],   muA, muB);
            unpack2(vAABB[j], eAA, eBB);
            unpack2(vAFBF[j], eAF, eBF);
            unpack2(vFFF[j],  muF, eFF);
            local += ssim_val(muA, muF, eAA, eFF, eAF);
            local += ssim_val(muB, muF, eBB, eFF, eBF);
        }
    }

    // ---- block reduction ----
    #pragma unroll
    for (int o = 16; o > 0; o >>= 1)
        local += __shfl_down_sync(0xffffffffu, local, o);
    if ((tid & 31) == 0) red[tid >> 5] = local;
    __syncthreads();

    const int bid = blockIdx.x + 16 * blockIdx.y + (16 * GRIDY) * blockIdx.z;
    __shared__ bool is_last;
    if (tid == 0) {
        float v = 0.f;
        #pragma unroll
        for (int w = 0; w < 8; w++) v += red[w];
        g_partials[bid] = v;
        __threadfence();
        unsigned int old = atomicAdd(&g_done, 1u);
        is_last = (old == NBLOCKS - 1);
    }
    __syncthreads();

    if (is_last) {
        double s = 0.0;
        for (int i = tid; i < NBLOCKS; i += NTHREADS)
            s += (double)__ldcg(&g_partials[i]);
        #pragma unroll
        for (int o = 16; o > 0; o >>= 1)
            s += __shfl_down_sync(0xffffffffu, s, o);
        double* redd = (double*)red;
        if ((tid & 31) == 0) redd[tid >> 5] = s;
        __syncthreads();
        if (tid == 0) {
            double t = 0.0;
            #pragma unroll
            for (int w = 0; w < 8; w++) t += redd[w];
            out[0] = (float)(0.5 * t / 12582912.0);
            g_done = 0;
        }
    }
}

extern "C" void kernel_launch(void* const* d_in, const int* in_sizes, int n_in,
                              void* d_out, int out_size) {
    const float* A = (const float*)d_in[0];
    const float* B = (const float*)d_in[1];
    const float* F = (const float*)d_in[2];

    GW gw;
    double gd[WIN], s = 0.0;
    for (int i = 0; i < WIN; i++) {
        double d = (double)(i - RAD);
        gd[i] = exp(-(d * d) / (2.0 * 1.5 * 1.5));
        s += gd[i];
    }
    for (int i = 0; i < WIN; i++) gw.g[i] = (float)(gd[i] / s);

    cudaFuncSetAttribute(ssim_tile_kernel,
                         cudaFuncAttributeMaxDynamicSharedMemorySize, SMEM_BYTES);

    dim3 grid(512 / TSX, GRIDY, 16 * 3);
    ssim_tile_kernel<<<grid, NTHREADS, SMEM_BYTES>>>(A, B, F, gw, (float*)d_out);
}